// round 12
// baseline (speedup 1.0000x reference)
#include <cuda_runtime.h>
#include <cuda_bf16.h>
#include <cstdint>

// VectorQuantizer N=65536, K=8192, D=256.
// R11: bf16 mma.sync filter, BN=128 (64 tiles), per-warp m32n32, split
// accumulator chains (16/warp). Exact fp32 rescore replicating R2 arithmetic
// bit-for-bit (rel_err 0.0).

typedef unsigned long long u64;
typedef uint32_t u32;

#define NN     65536
#define KC     8192
#define DD     256
#define BM     128
#define BN     128
#define NTILES (KC / BN)     // 64
#define NTHR   512
#define CAP    16
#define WIN    6e-4f
#define STRD   264           // bf16 elems per smem row (528 B; staggered banks)

__device__ __nv_bfloat16 g_zbf[(size_t)NN * DD];
__device__ __nv_bfloat16 g_ebf[(size_t)KC * DD];
__device__ float g_z2[NN];
__device__ float g_e2[KC];

// smem byte offsets
#define SA    0                          // 128*528 = 67584
#define SB0   67584                      // 128*528
#define SB1   135168
#define SE20  202752                     // 512
#define SE21  203264
#define SZ2   203776
#define SMIN  204288
#define SCNT  204800
#define SCD   205312                     // 128*16*4 = 8192
#define SCK   213504
#define SFI   221696
#define STOT  222208

__device__ __forceinline__ u32 s2u(const void* p) {
    u32 a;
    asm("{ .reg .u64 t; cvta.to.shared.u64 t, %1; cvt.u32.u64 %0, t; }"
        : "=r"(a) : "l"(p));
    return a;
}
__device__ __forceinline__ void cpa16(u32 dst, const void* src) {
    asm volatile("cp.async.ca.shared.global [%0], [%1], 16;\n" :: "r"(dst), "l"(src));
}
__device__ __forceinline__ void ldsm4(u32* r, u32 saddr) {
    asm volatile("ldmatrix.sync.aligned.m8n8.x4.shared.b16 {%0,%1,%2,%3}, [%4];"
                 : "=r"(r[0]), "=r"(r[1]), "=r"(r[2]), "=r"(r[3]) : "r"(saddr));
}
__device__ __forceinline__ void mma16816(float* c, const u32* a, const u32* b) {
    asm volatile("mma.sync.aligned.m16n8k16.row.col.f32.bf16.bf16.f32 "
                 "{%0,%1,%2,%3}, {%4,%5,%6,%7}, {%8,%9}, {%0,%1,%2,%3};"
                 : "+f"(c[0]), "+f"(c[1]), "+f"(c[2]), "+f"(c[3])
                 : "r"(a[0]), "r"(a[1]), "r"(a[2]), "r"(a[3]),
                   "r"(b[0]), "r"(b[1]));
}

// ---------------- merged prep kernel (z2/e2 accumulation order preserved!) ----------------
__global__ void prep_all(const float* __restrict__ z, const float* __restrict__ emb) {
    int b = blockIdx.x, lane = threadIdx.x;
    if (b < KC) {
        const float* r = emb + (size_t)b * DD;
        #pragma unroll
        for (int i = 0; i < DD / 32; ++i)
            g_ebf[(size_t)b * DD + lane + i * 32] = __float2bfloat16_rn(r[lane + i * 32]);
        if (lane == 0) {
            float s = 0.f;
            #pragma unroll 8
            for (int d = 0; d < DD; ++d) s = __fadd_rn(s, __fmul_rn(r[d], r[d]));
            g_e2[b] = s;
        }
    } else {
        int n = b - KC;
        const float* r = z + (size_t)n * DD;
        #pragma unroll
        for (int i = 0; i < DD / 32; ++i)
            g_zbf[(size_t)n * DD + lane + i * 32] = __float2bfloat16_rn(r[lane + i * 32]);
        if (lane == 0) {
            float s = 0.f;
            #pragma unroll 8
            for (int d = 0; d < DD; ++d) s = __fadd_rn(s, __fmul_rn(r[d], r[d]));
            g_z2[n] = s;
        }
    }
}

// ---------------- main kernel ----------------
__global__ __launch_bounds__(NTHR, 1)
void vq_main(const float* __restrict__ z, const float* __restrict__ emb,
             float* __restrict__ oq, float* __restrict__ ost,
             float* __restrict__ oidx)
{
    extern __shared__ char sm[];
    const u32 smb = s2u(sm);
    float* z2s    = (float*)(sm + SZ2);
    int*   rowMin = (int*)(sm + SMIN);
    int*   cnt    = (int*)(sm + SCNT);
    float* candD  = (float*)(sm + SCD);
    int*   candK  = (int*)(sm + SCK);
    int*   fidx   = (int*)(sm + SFI);

    const int tid  = threadIdx.x;
    const int wid  = tid >> 5;
    const int lane = tid & 31;
    const int rowbase = blockIdx.x * BM;
    const int Rw = (wid & 3) * 32;      // warp M offset (4 warps over M)
    const int Cw = (wid >> 2) * 32;     // warp N offset (4 warps over N=128)

    if (tid < BM) {
        rowMin[tid] = 0x7f7fffff;       // +FLT_MAX bits (distances positive)
        cnt[tid] = 0;
        z2s[tid] = g_z2[rowbase + tid];
    }

    // group 0: A tile + B tile 0 + e2 tile 0
    {
        const __nv_bfloat16* zb = g_zbf + (size_t)rowbase * DD;
        #pragma unroll 2
        for (int q = tid; q < BM * 32; q += NTHR) {
            int r = q >> 5, c = (q & 31) * 8;
            cpa16(smb + SA + (u32)((r * STRD + c) * 2), zb + (size_t)r * DD + c);
        }
        const __nv_bfloat16* eb = g_ebf;
        #pragma unroll 2
        for (int q = tid; q < BN * 32; q += NTHR) {
            int r = q >> 5, c = (q & 31) * 8;
            cpa16(smb + SB0 + (u32)((r * STRD + c) * 2), eb + (size_t)r * DD + c);
        }
        if (tid < 32) cpa16(smb + SE20 + tid * 16, g_e2 + tid * 4);
        asm volatile("cp.async.commit_group;\n" ::);
    }
    __syncthreads();

    // ldmatrix lane bases
    const int lrA = (lane & 7) + 8 * ((lane >> 3) & 1);
    const int kA  = 8 * (lane >> 4);
    const u32 aBase = smb + SA + (u32)(((Rw + lrA) * STRD + kA) * 2);
    const int lrB = (lane & 7) + 8 * (lane >> 4);
    const int kB  = 8 * ((lane >> 3) & 1);
    const u32 bOff = (u32)(((Cw + lrB) * STRD + kB) * 2);

    for (int t = 0; t < NTILES; ++t) {
        if (t + 1 < NTILES) {
            const __nv_bfloat16* eb = g_ebf + (size_t)(t + 1) * BN * DD;
            u32 bb  = smb + (((t + 1) & 1) ? SB1 : SB0);
            u32 e2d = smb + (((t + 1) & 1) ? SE21 : SE20);
            #pragma unroll 2
            for (int q = tid; q < BN * 32; q += NTHR) {
                int r = q >> 5, c = (q & 31) * 8;
                cpa16(bb + (u32)((r * STRD + c) * 2), eb + (size_t)r * DD + c);
            }
            if (tid < 32) cpa16(e2d + tid * 16, g_e2 + (t + 1) * BN + tid * 4);
            asm volatile("cp.async.commit_group;\n" ::);
            asm volatile("cp.async.wait_group 1;\n" ::);
        } else {
            asm volatile("cp.async.wait_group 0;\n" ::);
        }
        __syncthreads();

        const u32 bBase0 = smb + ((t & 1) ? SB1 : SB0) + bOff;
        const float* e2t = (const float*)(sm + ((t & 1) ? SE21 : SE20));

        // split accumulator chains: accL (ks 0-7), accH (ks 8-15)
        float accL[2][4][4], accH[2][4][4];
        #pragma unroll
        for (int mi = 0; mi < 2; ++mi)
            #pragma unroll
            for (int ni = 0; ni < 4; ++ni)
                #pragma unroll
                for (int c = 0; c < 4; ++c) { accL[mi][ni][c] = 0.f; accH[mi][ni][c] = 0.f; }

        #pragma unroll 2
        for (int ks = 0; ks < 8; ++ks) {
            u32 aT[2][4], bT[2][4];
            // low half (k = ks*16)
            ldsm4(aT[0], aBase + (u32)(ks * 32));
            ldsm4(aT[1], aBase + (u32)(16 * STRD * 2 + ks * 32));
            ldsm4(bT[0], bBase0 + (u32)(ks * 32));
            ldsm4(bT[1], bBase0 + (u32)(16 * STRD * 2 + ks * 32));
            #pragma unroll
            for (int mi = 0; mi < 2; ++mi) {
                mma16816(accL[mi][0], aT[mi], &bT[0][0]);
                mma16816(accL[mi][1], aT[mi], &bT[0][2]);
                mma16816(accL[mi][2], aT[mi], &bT[1][0]);
                mma16816(accL[mi][3], aT[mi], &bT[1][2]);
            }
            // high half (k = (ks+8)*16)
            ldsm4(aT[0], aBase + (u32)((ks + 8) * 32));
            ldsm4(aT[1], aBase + (u32)(16 * STRD * 2 + (ks + 8) * 32));
            ldsm4(bT[0], bBase0 + (u32)((ks + 8) * 32));
            ldsm4(bT[1], bBase0 + (u32)(16 * STRD * 2 + (ks + 8) * 32));
            #pragma unroll
            for (int mi = 0; mi < 2; ++mi) {
                mma16816(accH[mi][0], aT[mi], &bT[0][0]);
                mma16816(accH[mi][1], aT[mi], &bT[0][2]);
                mma16816(accH[mi][2], aT[mi], &bT[1][0]);
                mma16816(accH[mi][3], aT[mi], &bT[1][2]);
            }
        }

        // ---- epilogue: dv, row-min update, windowed inserts ----
        int cb = t * BN;
        float e2loc[4][2];
        #pragma unroll
        for (int ni = 0; ni < 4; ++ni) {
            float2 v = *(const float2*)(e2t + Cw + ni * 8 + (lane & 3) * 2);
            e2loc[ni][0] = v.x; e2loc[ni][1] = v.y;
        }
        #pragma unroll
        for (int mi = 0; mi < 2; ++mi) {
            #pragma unroll
            for (int s = 0; s < 2; ++s) {
                int r = Rw + mi * 16 + (lane >> 2) + 8 * s;
                float z2v = z2s[r];
                float mn = 3.4e38f;
                #pragma unroll
                for (int ni = 0; ni < 4; ++ni) {
                    #pragma unroll
                    for (int q = 0; q < 2; ++q) {
                        float dot = accL[mi][ni][2 * s + q] + accH[mi][ni][2 * s + q];
                        float dv = fmaf(-2.f, dot, z2v + e2loc[ni][q]);
                        accL[mi][ni][2 * s + q] = dv;   // reuse accL as dv store
                        mn = fminf(mn, dv);
                    }
                }
                if (__float_as_int(mn) < rowMin[r])
                    atomicMin(&rowMin[r], __float_as_int(mn));
            }
        }
        if (t == 0) __syncthreads();   // tile 0: establish thresholds first
        #pragma unroll
        for (int mi = 0; mi < 2; ++mi) {
            #pragma unroll
            for (int s = 0; s < 2; ++s) {
                int r = Rw + mi * 16 + (lane >> 2) + 8 * s;
                float thr = __int_as_float(rowMin[r]) + WIN;
                #pragma unroll
                for (int ni = 0; ni < 4; ++ni) {
                    #pragma unroll
                    for (int q = 0; q < 2; ++q) {
                        float dv = accL[mi][ni][2 * s + q];
                        if (dv <= thr) {
                            int pos = atomicAdd(&cnt[r], 1);
                            if (pos < CAP) {
                                candD[r * CAP + pos] = dv;
                                candK[r * CAP + pos] = cb + Cw + ni * 8 + (lane & 3) * 2 + q;
                            }
                        }
                    }
                }
            }
        }
        __syncthreads();
    }

    // ---- exact rescore (replicates R2 arithmetic exactly) ----
    if (tid < BM) {
        int r = tid;
        size_t n = (size_t)rowbase + r;
        int c = cnt[r];
        if (c > CAP) {
            fidx[r] = -1;
        } else {
            float thrF = __int_as_float(rowMin[r]) + WIN;
            float z2e = g_z2[n];
            const float* zr = z + n * DD;
            float bd = 0.f; int bk = -1;
            for (int i = 0; i < c; ++i) {
                if (candD[r * CAP + i] > thrF) continue;
                int k = candK[r * CAP + i];
                const float* er = emb + (size_t)k * DD;
                float lo = 0.f, hi = 0.f;
                #pragma unroll 4
                for (int d2 = 0; d2 < DD / 2; ++d2) {
                    lo = __fmaf_rn(__ldg(zr + 2 * d2),     __ldg(er + 2 * d2),     lo);
                    hi = __fmaf_rn(__ldg(zr + 2 * d2 + 1), __ldg(er + 2 * d2 + 1), hi);
                }
                float dot = __fadd_rn(lo, hi);
                float tt  = __fadd_rn(z2e, g_e2[k]);
                float dd  = __fadd_rn(tt, -2.0f * dot);
                if (bk < 0 || dd < bd || (dd == bd && k < bk)) { bd = dd; bk = k; }
            }
            fidx[r] = bk;
        }
    }
    __syncthreads();

    // ---- overflow fallback: full exact scan (cold) ----
    {
        float* redD = (float*)(sm + SB0);
        int*   redI = (int*)(sm + SB0 + NTHR * 4);
        for (int r = 0; r < BM; ++r) {
            if (fidx[r] != -1) continue;
            size_t n = (size_t)rowbase + r;
            const float* zr = z + n * DD;
            float z2e = g_z2[n];
            float bd = 0.f; int bk = -1;
            for (int k = tid; k < KC; k += NTHR) {
                const float* er = emb + (size_t)k * DD;
                float lo = 0.f, hi = 0.f;
                #pragma unroll 4
                for (int d2 = 0; d2 < DD / 2; ++d2) {
                    lo = __fmaf_rn(zr[2 * d2],     er[2 * d2],     lo);
                    hi = __fmaf_rn(zr[2 * d2 + 1], er[2 * d2 + 1], hi);
                }
                float dot = __fadd_rn(lo, hi);
                float dd  = __fadd_rn(__fadd_rn(z2e, g_e2[k]), -2.0f * dot);
                if (bk < 0 || dd < bd || (dd == bd && k < bk)) { bd = dd; bk = k; }
            }
            redD[tid] = bd; redI[tid] = bk;
            __syncthreads();
            if (tid == 0) {
                float B = redD[0]; int K2 = redI[0];
                for (int s2 = 1; s2 < NTHR; ++s2) {
                    float d = redD[s2]; int k2 = redI[s2];
                    if (k2 >= 0 && (K2 < 0 || d < B || (d == B && k2 < K2))) { B = d; K2 = k2; }
                }
                fidx[r] = K2;
            }
            __syncthreads();
        }
    }
    __syncthreads();

    // ---- outputs (512 threads: 2 rows per pass) ----
    for (int rr = 0; rr < BM; rr += 2) {
        int    r   = rr + (tid >> 8);
        int    c   = tid & 255;
        int    idx = fidx[r];
        size_t n   = (size_t)rowbase + r;
        float  qv  = __ldg(emb + (size_t)idx * DD + c);
        float  zv  = __ldg(z + n * DD + c);
        if (oq)  oq[n * DD + c]  = qv;
        if (ost) ost[n * DD + c] = __fadd_rn(__fadd_rn(qv, -zv), zv);
    }
    if (oidx && tid < BM)
        oidx[(size_t)rowbase + tid] = (float)fidx[tid];
}

extern "C" void kernel_launch(void* const* d_in, const int* in_sizes, int n_in,
                              void* d_out, int out_size)
{
    const float* z   = (const float*)d_in[0];
    const float* emb = (const float*)d_in[1];
    float* out = (float*)d_out;

    const int N = in_sizes[0] / DD;
    const size_t ND = (size_t)N * DD;

    float *oq = nullptr, *ost = nullptr, *oidx = nullptr;
    long osz = (long)out_size;
    if (osz >= (long)(2 * ND + N)) { oq = out; ost = out + ND; oidx = out + 2 * ND; }
    else if (osz == (long)(ND + N)) { oq = out; oidx = out + ND; }
    else if (osz == (long)ND)       { oq = out; }
    else if (osz == (long)N)        { oidx = out; }
    else                            { oq = out; }

    prep_all<<<KC + N, 32>>>(z, emb);

    cudaFuncSetAttribute(vq_main, cudaFuncAttributeMaxDynamicSharedMemorySize, STOT);
    vq_main<<<N / BM, NTHR, STOT>>>(z, emb, oq, ost, oidx);
}